// round 13
// baseline (speedup 1.0000x reference)
#include <cuda_runtime.h>
#include <math.h>

#define BB 32
#define NN 1024
#define DD 1024
#define HH 512
#define RR 64

typedef unsigned long long ull;

// ------------- scratch (device globals; allocation is forbidden) -------------
__device__ float g_pm[BB * DD];
__device__ float g_score[BB * NN];
__device__ float g_proj[(size_t)BB * NN * RR];    // 8 MB
__device__ float g_C[(size_t)BB * RR * 1024];     // 8 MB: C[b] = Mb[b] @ Bo
__device__ float g_hb[BB * DD];
__device__ float g_h1[BB * HH];
__device__ float g_lc[BB * HH];
__device__ float g_G[BB * RR * RR];
__device__ float g_L[BB * RR * RR];
__device__ float g_Mb[BB * RR * RR];
__device__ float g_part[8 * 32 * 4096];           // split-K partials

// ---------------- packed fp32 helpers (FFMA2) ----------------
__device__ __forceinline__ ull pk2(float a, float b) {
    ull r; asm("mov.b64 %0,{%1,%2};" : "=l"(r) : "f"(a), "f"(b)); return r;
}
__device__ __forceinline__ void fma2(ull& d, ull a, ull b) {
    asm("fma.rn.f32x2 %0,%1,%2,%0;" : "+l"(d) : "l"(a), "l"(b));
}
__device__ __forceinline__ float2 upk2(ull v) {
    float2 f; asm("mov.b64 {%0,%1},%2;" : "=f"(f.x), "=f"(f.y) : "l"(v)); return f;
}

// ================= K1: per-batch column mean over tokens 1..1023 ============
__global__ void k_colsum(const float* __restrict__ x) {
    int b = blockIdx.y;
    int d = blockIdx.x * 128 + threadIdx.x;
    const float* p = x + ((size_t)b << 20) + 1024 + d;
    float s0 = 0.f, s1 = 0.f, s2 = 0.f, s3 = 0.f;
    int t = 1;
    for (; t + 3 < 1024; t += 4) {
        s0 += p[0]; s1 += p[1024]; s2 += p[2048]; s3 += p[3072];
        p += 4096;
    }
    for (; t < 1024; t++) { s0 += *p; p += 1024; }
    g_pm[(b << 10) + d] = (s0 + s1 + s2 + s3) * (1.0f / 1023.0f);
}

// ========== K2: proj = x @ Bi^T, 128x64 tiles, packed-operand FFMA2 =========
// grid (8, 32), 256 threads
// x_s: k-major [32][132] -> token pairs contiguous (LDS as ulonglong2)
// b2u: pre-duplicated (b,b) ull pairs [32][64]
__global__ void k_proj(const float* __restrict__ x, const float* __restrict__ Bi) {
    __shared__ __align__(16) float x_s[32 * 132];
    __shared__ __align__(16) ull   b2u[32 * 64];
    __shared__ float pm_s[32];
    int b = blockIdx.y, t0 = blockIdx.x * 128, tid = threadIdx.x;
    int tr = (tid >> 4) << 3;        // token base (pairs: tr..tr+7)
    int rc = (tid & 15) << 2;        // r base (4 columns)
    ull acc[4][4];
#pragma unroll
    for (int i = 0; i < 4; i++)
#pragma unroll
        for (int j = 0; j < 4; j++) acc[i][j] = 0ull;
    float sacc = 0.f;                 // distributed score: token tid>>1, half (tid&1)
    int st_tok = tid >> 1, st_kh = (tid & 1) << 4;
    size_t xb = (((size_t)b << 10) + t0) << 10;

    for (int kc = 0; kc < 1024; kc += 32) {
        __syncthreads();
        // x tile: 128 tokens x 32 k -> k-major scatter (4 STS.32 per LDG.128)
#pragma unroll
        for (int s = 0; s < 4; s++) {
            int e = tid + (s << 8);
            int t = e >> 3, kq = e & 7;
            float4 v = *(const float4*)&x[xb + ((size_t)t << 10) + kc + (kq << 2)];
            x_s[((kq << 2) + 0) * 132 + t] = v.x;
            x_s[((kq << 2) + 1) * 132 + t] = v.y;
            x_s[((kq << 2) + 2) * 132 + t] = v.z;
            x_s[((kq << 2) + 3) * 132 + t] = v.w;
        }
        // Bi tile: 64 r x 32 k -> duplicated ull pairs
#pragma unroll
        for (int s = 0; s < 2; s++) {
            int e = tid + (s << 8);
            int r = e >> 3, kq = e & 7;
            float4 v = *(const float4*)&Bi[(r << 10) + kc + (kq << 2)];
            b2u[((kq << 2) + 0) * 64 + r] = pk2(v.x, v.x);
            b2u[((kq << 2) + 1) * 64 + r] = pk2(v.y, v.y);
            b2u[((kq << 2) + 2) * 64 + r] = pk2(v.z, v.z);
            b2u[((kq << 2) + 3) * 64 + r] = pk2(v.w, v.w);
        }
        if (tid < 32) pm_s[tid] = g_pm[(b << 10) + kc + tid];
        __syncthreads();

        // distributed score: 2 threads per token, 16 k each
#pragma unroll
        for (int j = 0; j < 16; j++) {
            float v = x_s[(st_kh + j) * 132 + st_tok] - pm_s[st_kh + j];
            sacc += v * v;
        }

#pragma unroll
        for (int k = 0; k < 32; k++) {
            ulonglong2 xA = *(const ulonglong2*)&x_s[k * 132 + tr];      // t0t1, t2t3
            ulonglong2 xB = *(const ulonglong2*)&x_s[k * 132 + tr + 4];  // t4t5, t6t7
            ulonglong2 bA = *(const ulonglong2*)&b2u[k * 64 + rc];       // r0, r1 (dup)
            ulonglong2 bB = *(const ulonglong2*)&b2u[k * 64 + rc + 2];   // r2, r3 (dup)
            fma2(acc[0][0], xA.x, bA.x); fma2(acc[0][1], xA.x, bA.y);
            fma2(acc[0][2], xA.x, bB.x); fma2(acc[0][3], xA.x, bB.y);
            fma2(acc[1][0], xA.y, bA.x); fma2(acc[1][1], xA.y, bA.y);
            fma2(acc[1][2], xA.y, bB.x); fma2(acc[1][3], xA.y, bB.y);
            fma2(acc[2][0], xB.x, bA.x); fma2(acc[2][1], xB.x, bA.y);
            fma2(acc[2][2], xB.x, bB.x); fma2(acc[2][3], xB.x, bB.y);
            fma2(acc[3][0], xB.y, bA.x); fma2(acc[3][1], xB.y, bA.y);
            fma2(acc[3][2], xB.y, bB.x); fma2(acc[3][3], xB.y, bB.y);
        }
    }
    // epilogue: unpack token pairs -> row-major float4 stores
    size_t pb = (((size_t)b << 10) + t0 + tr) * 64 + rc;
#pragma unroll
    for (int tp = 0; tp < 4; tp++) {
        float2 v0 = upk2(acc[tp][0]), v1 = upk2(acc[tp][1]);
        float2 v2 = upk2(acc[tp][2]), v3 = upk2(acc[tp][3]);
        *(float4*)&g_proj[pb + (size_t)(2 * tp) * 64]     = make_float4(v0.x, v1.x, v2.x, v3.x);
        *(float4*)&g_proj[pb + (size_t)(2 * tp + 1) * 64] = make_float4(v0.y, v1.y, v2.y, v3.y);
    }
    // combine per-token score halves
    sacc += __shfl_xor_sync(0xffffffffu, sacc, 1);
    if ((tid & 1) == 0) {
        int t = t0 + st_tok;
        g_score[(b << 10) + t] = (t == 0) ? -3.0e38f : sacc * (1.f / 1024.f);
    }
}

// ========== K3: per-batch top4 + detail + LayerNorm -> g_hb =================
__global__ void k_prep1(const float* __restrict__ x,
                        const float* __restrict__ lng, const float* __restrict__ lnb) {
    __shared__ float sc[1024];
    __shared__ float det[1024];
    __shared__ float rv[256];
    __shared__ int   ri[256];
    __shared__ int   topi[4];
    __shared__ float st2[2];
    int b = blockIdx.x, tid = threadIdx.x;

    for (int i = tid; i < 1024; i += 256) sc[i] = g_score[(b << 10) + i];
    __syncthreads();
    for (int rd = 0; rd < 4; rd++) {
        float bv = -3.4e38f; int bi = 1 << 30;
        for (int i = tid; i < 1024; i += 256) {
            float v = sc[i];
            if (v > bv || (v == bv && i < bi)) { bv = v; bi = i; }
        }
        rv[tid] = bv; ri[tid] = bi;
        __syncthreads();
        for (int off = 128; off; off >>= 1) {
            if (tid < off) {
                float v2 = rv[tid + off]; int i2 = ri[tid + off];
                if (v2 > rv[tid] || (v2 == rv[tid] && i2 < ri[tid])) { rv[tid] = v2; ri[tid] = i2; }
            }
            __syncthreads();
        }
        if (tid == 0) { topi[rd] = ri[0]; sc[ri[0]] = -3.4e38f; }
        __syncthreads();
    }
    int t0 = topi[0], t1 = topi[1], t2 = topi[2], t3 = topi[3];
    size_t xb = ((size_t)b << 20);
    for (int d = tid; d < 1024; d += 256)
        det[d] = 0.25f * (x[xb + ((size_t)t0 << 10) + d] + x[xb + ((size_t)t1 << 10) + d] +
                          x[xb + ((size_t)t2 << 10) + d] + x[xb + ((size_t)t3 << 10) + d]);
    __syncthreads();
    float s = 0.f, q = 0.f;
    for (int d = tid; d < 1024; d += 256) { float v = det[d]; s += v; q += v * v; }
    rv[tid] = s; __syncthreads();
    for (int off = 128; off; off >>= 1) { if (tid < off) rv[tid] += rv[tid + off]; __syncthreads(); }
    if (tid == 0) st2[0] = rv[0] * (1.f / 1024.f);
    __syncthreads();
    rv[tid] = q; __syncthreads();
    for (int off = 128; off; off >>= 1) { if (tid < off) rv[tid] += rv[tid + off]; __syncthreads(); }
    if (tid == 0) { float mu = st2[0]; st2[1] = rv[0] * (1.f / 1024.f) - mu * mu; }
    __syncthreads();
    float mu = st2[0], inv = rsqrtf(st2[1] + 1e-5f);
    for (int d = tid; d < 1024; d += 256)
        g_hb[(b << 10) + d] = (det[d] - mu) * inv * lng[d] + lnb[d];
}

// ========== K4: split-K small GEMM partial: (32 x CH) @ (CH x 64tile) =======
__global__ void k_sgK(const float* __restrict__ Aext, const float* __restrict__ W,
                      int N, int mode) {
    __shared__ __align__(16) float in_s[32 * 33];
    __shared__ __align__(16) float w_s[32 * 68];
    const float* A = (mode == 0) ? g_hb : (mode == 1) ? g_h1 : (mode == 2) ? Aext : g_lc;
    int lda = (mode == 0) ? 1024 : 512;
    int tid = threadIdx.x, n0 = blockIdx.x * 64;
    int kc0 = blockIdx.y * 128;
    int rg = (tid >> 4) << 1, cg = (tid & 15) << 2;
    float a[2][4] = {};
    for (int kc = kc0; kc < kc0 + 128; kc += 32) {
        __syncthreads();
#pragma unroll
        for (int s = 0; s < 4; s++) {
            int e = tid + (s << 8);
            int row = e >> 5, k = e & 31;
            in_s[k * 33 + row] = A[row * lda + kc + k];
        }
#pragma unroll
        for (int s = 0; s < 8; s++) {
            int e = tid + (s << 8);
            int k = e >> 6, nn = e & 63;
            w_s[k * 68 + nn] = W[(size_t)(kc + k) * N + n0 + nn];
        }
        __syncthreads();
#pragma unroll
        for (int k = 0; k < 32; k++) {
            float4 wv = *(const float4*)&w_s[k * 68 + cg];
            float i0 = in_s[k * 33 + rg], i1 = in_s[k * 33 + rg + 1];
            a[0][0] += i0 * wv.x; a[0][1] += i0 * wv.y; a[0][2] += i0 * wv.z; a[0][3] += i0 * wv.w;
            a[1][0] += i1 * wv.x; a[1][1] += i1 * wv.y; a[1][2] += i1 * wv.z; a[1][3] += i1 * wv.w;
        }
    }
    size_t pb = (size_t)blockIdx.y * 32 * N;
    int n = n0 + cg;
#pragma unroll
    for (int i = 0; i < 2; i++)
#pragma unroll
        for (int j = 0; j < 4; j++)
            g_part[pb + (size_t)(rg + i) * N + n + j] = a[i][j];
}

// ========== K5: reduce split-K partials + bias [+gelu] ======================
__global__ void k_red(const float* __restrict__ bias, int C, int N, int mode) {
    int e = blockIdx.x * 256 + threadIdx.x;
    if (e >= 32 * N) return;
    float s = 0.f;
    for (int c = 0; c < C; c++) s += g_part[(size_t)c * 32 * N + e];
    s += bias[e % N];
    if (mode == 0) s = 0.5f * s * (1.f + erff(s * 0.7071067811865475f));
    float* dst = (mode == 0) ? g_h1 : (mode == 1) ? g_lc : (mode == 2) ? g_G : g_L;
    dst[e] = s;
}

// ------------- 64x64 smem matmul, 256 threads, 4x4 tile (pad 68) ------------
__device__ __forceinline__ void mm64(float* __restrict__ C, const float* __restrict__ A,
                                     const float* __restrict__ Bm, int tid) {
    int i0 = (tid >> 4) << 2, j0 = (tid & 15) << 2;
    float a[4][4] = {};
#pragma unroll 4
    for (int m = 0; m < 64; m++) {
        float4 bv = *(const float4*)&Bm[m * 68 + j0];
        float r0 = A[(i0 + 0) * 68 + m], r1 = A[(i0 + 1) * 68 + m];
        float r2 = A[(i0 + 2) * 68 + m], r3 = A[(i0 + 3) * 68 + m];
        a[0][0] += r0 * bv.x; a[0][1] += r0 * bv.y; a[0][2] += r0 * bv.z; a[0][3] += r0 * bv.w;
        a[1][0] += r1 * bv.x; a[1][1] += r1 * bv.y; a[1][2] += r1 * bv.z; a[1][3] += r1 * bv.w;
        a[2][0] += r2 * bv.x; a[2][1] += r2 * bv.y; a[2][2] += r2 * bv.z; a[2][3] += r2 * bv.w;
        a[3][0] += r3 * bv.x; a[3][1] += r3 * bv.y; a[3][2] += r3 * bv.z; a[3][3] += r3 * bv.w;
    }
#pragma unroll
    for (int i = 0; i < 4; i++)
        *(float4*)&C[(i0 + i) * 68 + j0] = make_float4(a[i][0], a[i][1], a[i][2], a[i][3]);
}

// ========== K6: heads + omega + expm + Mb (per batch) =======================
__global__ void k_omega(const float* __restrict__ ctx,
                        const float* __restrict__ wm, const float* __restrict__ bm,
                        const float* __restrict__ wgain, const float* __restrict__ bgain,
                        const float* __restrict__ pwgate, const float* __restrict__ pbgate,
                        const float* __restrict__ pwa, const float* __restrict__ pba,
                        const float* __restrict__ pwb, const float* __restrict__ pbb) {
    extern __shared__ __align__(16) float sm[];
    float* fused = sm;             // 1024
    float* smm = sm + 1024;        // 64
    float* sgn = sm + 1088;        // 64
    float* red = sm + 1152;        // 256
    float* ssc = sm + 1408;        // 16
    float* B0 = sm + 1424;         // 6 buffers of 64*68
    float* B1 = B0 + 4352;
    float* B2 = B1 + 4352;
    float* B3 = B2 + 4352;
    float* B4 = B3 + 4352;
    float* B5 = B4 + 4352;
    int b = blockIdx.x, tid = threadIdx.x;

    for (int i = tid; i < 512; i += 256) {
        fused[i] = ctx[b * 512 + i];
        fused[512 + i] = g_lc[b * 512 + i];
    }
    __syncthreads();
    {   // mode mask + gains
        int r = tid & 63, qd = tid >> 6;
        float acc = 0.f;
        for (int i = qd * 256; i < qd * 256 + 256; i++) acc += fused[i] * wm[i * 64 + r];
        red[tid] = acc; __syncthreads();
        if (tid < 64) {
            float sv = red[tid] + red[tid + 64] + red[tid + 128] + red[tid + 192] + bm[tid];
            smm[tid] = 1.f / (1.f + expf(-sv));
        }
        __syncthreads();
        acc = 0.f;
        for (int i = qd * 256; i < qd * 256 + 256; i++) acc += fused[i] * wgain[i * 64 + r];
        red[tid] = acc; __syncthreads();
        if (tid < 64) {
            float sv = red[tid] + red[tid + 64] + red[tid + 128] + red[tid + 192] + bgain[tid];
            sgn[tid] = 1.f + 0.1f * tanhf(sv);
        }
        __syncthreads();
    }
    {   // scalar heads
        float pa = 0.f, pb = 0.f, pg = 0.f;
        for (int i = tid; i < 1024; i += 256) {
            float f = fused[i];
            pa += f * pwa[i]; pb += f * pwb[i]; pg += f * pwgate[i];
        }
        red[tid] = pa; __syncthreads();
        for (int off = 128; off; off >>= 1) { if (tid < off) red[tid] += red[tid + off]; __syncthreads(); }
        if (tid == 0) ssc[0] = red[0];
        __syncthreads();
        red[tid] = pb; __syncthreads();
        for (int off = 128; off; off >>= 1) { if (tid < off) red[tid] += red[tid + off]; __syncthreads(); }
        if (tid == 0) ssc[1] = red[0];
        __syncthreads();
        red[tid] = pg; __syncthreads();
        for (int off = 128; off; off >>= 1) { if (tid < off) red[tid] += red[tid + off]; __syncthreads(); }
        if (tid == 0) ssc[2] = red[0];
        __syncthreads();
    }
    float alpha = 0.5f / (1.f + expf(-(ssc[0] + pba[0])));
    float a2c = alpha * 0.5f;
    float b12 = 0.25f * tanhf(ssc[1] + pbb[0]) * (1.f / 12.f);
    float gate = 1.f / (1.f + expf(-(ssc[2] + pbgate[0])));

    {   // masked skews: B1 = mg, B2 = ml
        const float* Gp = g_G + b * 4096;
        const float* Lp = g_L + b * 4096;
        for (int e = tid; e < 4096; e += 256) {
            int i = e >> 6, j = e & 63;
            float w = smm[i] * smm[j];
            B1[i * 68 + j] = w * 0.5f * (Gp[i * 64 + j] - Gp[j * 64 + i]);
            B2[i * 68 + j] = w * 0.5f * (Lp[i * 64 + j] - Lp[j * 64 + i]);
        }
    }
    __syncthreads();
    mm64(B3, B2, B1, tid);   // P = ml @ mg; comm = P - P^T
    __syncthreads();
    for (int e = tid; e < 4096; e += 256) {
        int i = e >> 6, j = e & 63;
        B0[i * 68 + j] = a2c * (B1[i * 68 + j] + B2[i * 68 + j]) +
                         b12 * (B3[i * 68 + j] - B3[j * 68 + i]);
    }
    __syncthreads();
    // 1-norm and scaling
    if (tid < 64) {
        float sv = 0.f;
        for (int i = 0; i < 64; i++) sv += fabsf(B0[i * 68 + tid]);
        red[tid] = sv;
    }
    __syncthreads();
    for (int off = 32; off; off >>= 1) {
        if (tid < off && tid + off < 64) red[tid] = fmaxf(red[tid], red[tid + off]);
        __syncthreads();
    }
    float nrm = red[0];
    int sexp = 0;
    if (nrm > 0.5f) {
        sexp = (int)ceilf(log2f(nrm * 2.0f));
        if (sexp < 0) sexp = 0;
        if (sexp > 30) sexp = 30;
    }
    float scl = exp2f(-(float)sexp);
    for (int e = tid; e < 4096; e += 256) { int i = e >> 6, j = e & 63; B0[i * 68 + j] *= scl; }
    __syncthreads();
    // degree-8 Paterson-Stockmeyer Taylor
    mm64(B1, B0, B0, tid); __syncthreads();      // A2
    mm64(B2, B1, B0, tid); __syncthreads();      // A3
    mm64(B3, B1, B1, tid); __syncthreads();      // A4
    for (int e = tid; e < 4096; e += 256) {
        int i = e >> 6, j = e & 63;
        float dI = (i == j) ? 1.f : 0.f;
        B4[i * 68 + j] = dI * (1.f / 24.f) + B0[i * 68 + j] * (1.f / 120.f) +
                         B1[i * 68 + j] * (1.f / 720.f) + B2[i * 68 + j] * (1.f / 5040.f) +
                         B3[i * 68 + j] * (1.f / 40320.f);
    }
    __syncthreads();
    mm64(B5, B3, B4, tid); __syncthreads();      // A4*U
    for (int e = tid; e < 4096; e += 256) {
        int i = e >> 6, j = e & 63;
        float dI = (i == j) ? 1.f : 0.f;
        B3[i * 68 + j] = dI + B0[i * 68 + j] + 0.5f * B1[i * 68 + j] +
                         (1.f / 6.f) * B2[i * 68 + j] + B5[i * 68 + j];
    }
    __syncthreads();
    float* Tc = B3; float* Tw = B4;
    for (int it = 0; it < sexp; it++) {
        mm64(Tw, Tc, Tc, tid);
        __syncthreads();
        float* t = Tc; Tc = Tw; Tw = t;
    }
    // Mb = gate * (Q * diag(gains) - I)
    for (int e = tid; e < 4096; e += 256) {
        int i = e >> 6, j = e & 63;
        g_Mb[b * 4096 + e] = gate * (Tc[i * 68 + j] * sgn[j] - ((i == j) ? 1.f : 0.f));
    }
}

// ========== K7: C[b] = Mb[b] @ Bo  (64x64 @ 64x1024) ========================
__global__ void k_mbo(const float* __restrict__ Bo) {
    __shared__ __align__(16) float m_s[64 * 68];
    __shared__ __align__(16) float bo_s[64 * 68];
    int b = blockIdx.y, oc0 = blockIdx.x * 64, tid = threadIdx.x;
#pragma unroll
    for (int s = 0; s < 16; s++) {
        int e = tid + (s << 8);
        int i = e >> 6, j = e & 63;
        m_s[i * 68 + j] = g_Mb[b * 4096 + e];
        bo_s[i * 68 + j] = Bo[(size_t)i * 1024 + oc0 + j];
    }
    __syncthreads();
    int r0 = (tid >> 4) << 2, c0 = (tid & 15) << 2;
    float a[4][4] = {};
#pragma unroll 4
    for (int k = 0; k < 64; k++) {
        float4 bv = *(const float4*)&bo_s[k * 68 + c0];
        float m0 = m_s[(r0 + 0) * 68 + k], m1 = m_s[(r0 + 1) * 68 + k];
        float m2 = m_s[(r0 + 2) * 68 + k], m3 = m_s[(r0 + 3) * 68 + k];
        a[0][0] += m0 * bv.x; a[0][1] += m0 * bv.y; a[0][2] += m0 * bv.z; a[0][3] += m0 * bv.w;
        a[1][0] += m1 * bv.x; a[1][1] += m1 * bv.y; a[1][2] += m1 * bv.z; a[1][3] += m1 * bv.w;
        a[2][0] += m2 * bv.x; a[2][1] += m2 * bv.y; a[2][2] += m2 * bv.z; a[2][3] += m2 * bv.w;
        a[3][0] += m3 * bv.x; a[3][1] += m3 * bv.y; a[3][2] += m3 * bv.z; a[3][3] += m3 * bv.w;
    }
    size_t cb = ((size_t)b << 16);
#pragma unroll
    for (int i = 0; i < 4; i++)
        *(float4*)&g_C[cb + (size_t)(r0 + i) * 1024 + oc0 + c0] =
            make_float4(a[i][0], a[i][1], a[i][2], a[i][3]);
}

// ========== K8: out[b] = proj[b] @ C[b], packed-operand FFMA2 ===============
// grid (16, 256): y -> b = y>>3, t0 = (y&7)*128
// a_s: proj k-major [64][132]; c2u: C pre-duplicated ull [64][64]
__global__ void k_fin(float* __restrict__ out) {
    extern __shared__ __align__(16) float smf[];
    float* a_s = smf;                         // 64 * 132 floats
    ull*   c2u = (ull*)(smf + 64 * 132);      // 64 * 64 ulls
    int oc0 = blockIdx.x * 64;
    int b = blockIdx.y >> 3;
    int t0 = (blockIdx.y & 7) << 7;
    size_t T0 = ((size_t)b << 10) + t0;
    size_t cb = ((size_t)b << 16);
    int tid = threadIdx.x;
    // proj tile: 128 tokens x 64 k -> k-major scatter
#pragma unroll
    for (int s = 0; s < 8; s++) {
        int e = tid + (s << 8);
        int t = e >> 4, kq = e & 15;
        float4 v = *(const float4*)&g_proj[(T0 + t) * 64 + (kq << 2)];
        a_s[((kq << 2) + 0) * 132 + t] = v.x;
        a_s[((kq << 2) + 1) * 132 + t] = v.y;
        a_s[((kq << 2) + 2) * 132 + t] = v.z;
        a_s[((kq << 2) + 3) * 132 + t] = v.w;
    }
    // C tile: 64 r x 64 oc -> duplicated ulls
#pragma unroll
    for (int s = 0; s < 4; s++) {
        int e = tid + (s << 8);
        int r = e >> 4, cq = e & 15;
        float4 v = *(const float4*)&g_C[cb + (size_t)r * 1024 + oc0 + (cq << 2)];
        c2u[r * 64 + (cq << 2) + 0] = pk2(v.x, v.x);
        c2u[r * 64 + (cq << 2) + 1] = pk2(v.y, v.y);
        c2u[r * 64 + (cq << 2) + 2] = pk2(v.z, v.z);
        c2u[r * 64 + (cq << 2) + 3] = pk2(v.w, v.w);
    }
    __syncthreads();
    int tr = (tid >> 4) << 3;      // token base (pairs)
    int c0 = (tid & 15) << 2;      // oc base
    ull acc[4][4];
#pragma unroll
    for (int i = 0; i < 4; i++)
#pragma unroll
        for (int j = 0; j < 4; j++) acc[i][j] = 0ull;
#pragma unroll 4
    for (int k = 0; k < 64; k++) {
        ulonglong2 xA = *(const ulonglong2*)&a_s[k * 132 + tr];
        ulonglong2 xB = *(const ulonglong2*)&a_s[k * 132 + tr + 4];
        ulonglong2 cA = *(const ulonglong2*)&c2u[k * 64 + c0];
        ulonglong2 cB = *(const ulonglong2*)&c2u[k * 64 + c0 + 2];
        fma2(acc[0][0], xA.x, cA.x); fma2(acc[0][1], xA.x, cA.y);
        fma2(acc[0][2], xA.x, cB.x); fma2(acc[0][3], xA.x, cB.y);
        fma2(acc[1][0], xA.y, cA.x); fma2(acc[1][1], xA.y, cA.y);
        fma2(acc[1][2], xA.y, cB.x); fma2(acc[1][3], xA.y, cB.y);
        fma2(acc[2][0], xB.x, cA.x); fma2(acc[2][1], xB.x, cA.y);
        fma2(acc[2][2], xB.x, cB.x); fma2(acc[2][3], xB.x, cB.y);
        fma2(acc[3][0], xB.y, cA.x); fma2(acc[3][1], xB.y, cA.y);
        fma2(acc[3][2], xB.y, cB.x); fma2(acc[3][3], xB.y, cB.y);
    }
#pragma unroll
    for (int tp = 0; tp < 4; tp++) {
        float2 v0 = upk2(acc[tp][0]), v1 = upk2(acc[tp][1]);
        float2 v2 = upk2(acc[tp][2]), v3 = upk2(acc[tp][3]);
        *(float4*)&out[(T0 + tr + 2 * tp) * 1024 + oc0 + c0] =
            make_float4(v0.x, v1.x, v2.x, v3.x);
        *(float4*)&out[(T0 + tr + 2 * tp + 1) * 1024 + oc0 + c0] =
            make_float4(v0.y, v1.y, v2.y, v3.y);
    }
}

// =============================== launch =====================================
extern "C" void kernel_launch(void* const* d_in, const int* in_sizes, int n_in,
                              void* d_out, int out_size) {
    const float* x     = (const float*)d_in[0];
    const float* ctx   = (const float*)d_in[1];
    const float* Bi    = (const float*)d_in[2];
    const float* Bo    = (const float*)d_in[3];
    const float* lng   = (const float*)d_in[4];
    const float* lnb   = (const float*)d_in[5];
    const float* w1    = (const float*)d_in[6];
    const float* b1    = (const float*)d_in[7];
    const float* w2    = (const float*)d_in[8];
    const float* b2    = (const float*)d_in[9];
    const float* wg    = (const float*)d_in[10];
    const float* bg    = (const float*)d_in[11];
    const float* wl    = (const float*)d_in[12];
    const float* bl    = (const float*)d_in[13];
    const float* wm    = (const float*)d_in[14];
    const float* bm    = (const float*)d_in[15];
    const float* wgain = (const float*)d_in[16];
    const float* bgain = (const float*)d_in[17];
    const float* wgate = (const float*)d_in[18];
    const float* bgate = (const float*)d_in[19];
    const float* wa    = (const float*)d_in[20];
    const float* ba    = (const float*)d_in[21];
    const float* wb    = (const float*)d_in[22];
    const float* wbb   = (const float*)d_in[23];
    float* out = (float*)d_out;

    const int OMEGA_SMEM = (1424 + 6 * 4352) * 4;            // 110144 bytes
    const int FIN_SMEM   = 64 * 132 * 4 + 64 * 64 * 8;       // 33792 + 32768 = 66560
    cudaFuncSetAttribute(k_omega, cudaFuncAttributeMaxDynamicSharedMemorySize, OMEGA_SMEM);
    cudaFuncSetAttribute(k_fin,   cudaFuncAttributeMaxDynamicSharedMemorySize, FIN_SMEM);

    k_colsum<<<dim3(8, 32), 128>>>(x);
    k_proj<<<dim3(8, 32), 256>>>(x, Bi);
    k_prep1<<<32, 256>>>(x, lng, lnb);

    // MLP1: hb @ w1 (K=1024 -> 8 chunks), gelu
    k_sgK<<<dim3(8, 8), 256>>>(nullptr, w1, 512, 0);
    k_red<<<64, 256>>>(b1, 8, 512, 0);
    // MLP2: h1 @ w2 (K=512 -> 4 chunks)
    k_sgK<<<dim3(8, 4), 256>>>(nullptr, w2, 512, 1);
    k_red<<<64, 256>>>(b2, 4, 512, 1);
    // ctx @ wg -> G
    k_sgK<<<dim3(64, 4), 256>>>(ctx, wg, 4096, 2);
    k_red<<<512, 256>>>(bg, 4, 4096, 2);
    // lc @ wl -> L
    k_sgK<<<dim3(64, 4), 256>>>(nullptr, wl, 4096, 3);
    k_red<<<512, 256>>>(bl, 4, 4096, 3);

    k_omega<<<32, 256, OMEGA_SMEM>>>(ctx, wm, bm, wgain, bgain,
                                     wgate, bgate, wa, ba, wb, wbb);
    k_mbo<<<dim3(16, 32), 256>>>(Bo);
    k_fin<<<dim3(16, 256), 256, FIN_SMEM>>>(out);
}

// round 14
// speedup vs baseline: 1.4711x; 1.4711x over previous
#include <cuda_runtime.h>
#include <math.h>

#define BB 32
#define NN 1024
#define DD 1024
#define HH 512
#define RR 64

typedef unsigned long long ull;

// ------------- scratch (device globals; allocation is forbidden) -------------
__device__ float g_pm[BB * DD];
__device__ float g_score[BB * NN];
__device__ float g_proj[(size_t)BB * NN * RR];    // 8 MB
__device__ float g_C[(size_t)BB * RR * 1024];     // 8 MB: C[b] = Mb[b] @ Bo
__device__ float g_hb[BB * DD];
__device__ float g_h1[BB * HH];
__device__ float g_lc[BB * HH];
__device__ float g_G[BB * RR * RR];
__device__ float g_L[BB * RR * RR];
__device__ float g_Mb[BB * RR * RR];
__device__ float g_part[8 * 32 * 4096];           // split-K partials

// ---------------- packed fp32 helpers (FFMA2) ----------------
__device__ __forceinline__ ull pk2(float a, float b) {
    ull r; asm("mov.b64 %0,{%1,%2};" : "=l"(r) : "f"(a), "f"(b)); return r;
}
__device__ __forceinline__ void fma2(ull& d, ull a, ull b) {
    asm("fma.rn.f32x2 %0,%1,%2,%0;" : "+l"(d) : "l"(a), "l"(b));
}
__device__ __forceinline__ float2 upk2(ull v) {
    float2 f; asm("mov.b64 {%0,%1},%2;" : "=f"(f.x), "=f"(f.y) : "l"(v)); return f;
}

// ================= K1: per-batch column mean over tokens 1..1023 ============
__global__ void k_colsum(const float* __restrict__ x) {
    int b = blockIdx.y;
    int d = blockIdx.x * 128 + threadIdx.x;
    const float* p = x + ((size_t)b << 20) + 1024 + d;
    float s0 = 0.f, s1 = 0.f, s2 = 0.f, s3 = 0.f;
    int t = 1;
    for (; t + 3 < 1024; t += 4) {
        s0 += p[0]; s1 += p[1024]; s2 += p[2048]; s3 += p[3072];
        p += 4096;
    }
    for (; t < 1024; t++) { s0 += *p; p += 1024; }
    g_pm[(b << 10) + d] = (s0 + s1 + s2 + s3) * (1.0f / 1023.0f);
}

// ========== K2: proj = x @ Bi^T, 128x64 tiles, FFMA2, distributed score =====
// grid (8, 32), 256 threads (R12 layout: token-major x_s, k-major b_s)
__global__ void k_proj(const float* __restrict__ x, const float* __restrict__ Bi) {
    __shared__ __align__(16) float x_s[128 * 36];   // token-major [t][k], pad 36
    __shared__ __align__(16) float b_s[32 * 68];    // k-major [k][r], pad 68
    __shared__ float pm_s[32];
    int b = blockIdx.y, t0 = blockIdx.x * 128, tid = threadIdx.x;
    int tr = (tid >> 4) << 3, rc = (tid & 15) << 2;
    ull acc[8][2];
#pragma unroll
    for (int i = 0; i < 8; i++) { acc[i][0] = 0ull; acc[i][1] = 0ull; }
    float sacc = 0.f;                 // distributed score: token tid>>1, k-half tid&1
    int st_tok = tid >> 1, st_kh = (tid & 1) << 4;
    size_t xb = (((size_t)b << 10) + t0) << 10;

    for (int kc = 0; kc < 1024; kc += 32) {
        __syncthreads();
#pragma unroll
        for (int s = 0; s < 4; s++) {
            int e = tid + (s << 8);
            int t = e >> 3, kq = e & 7;
            float4 v = *(const float4*)&x[xb + ((size_t)t << 10) + kc + (kq << 2)];
            *(float4*)&x_s[t * 36 + (kq << 2)] = v;
        }
#pragma unroll
        for (int s = 0; s < 2; s++) {
            int e = tid + (s << 8);
            int r = e >> 3, kq = e & 7;
            float4 v = *(const float4*)&Bi[(r << 10) + kc + (kq << 2)];
            b_s[((kq << 2) + 0) * 68 + r] = v.x;
            b_s[((kq << 2) + 1) * 68 + r] = v.y;
            b_s[((kq << 2) + 2) * 68 + r] = v.z;
            b_s[((kq << 2) + 3) * 68 + r] = v.w;
        }
        if (tid < 32) pm_s[tid] = g_pm[(b << 10) + kc + tid];
        __syncthreads();

        // distributed score: 2 threads per token, 16 k each
#pragma unroll
        for (int j = 0; j < 16; j++) {
            float v = x_s[st_tok * 36 + st_kh + j] - pm_s[st_kh + j];
            sacc += v * v;
        }

#pragma unroll
        for (int k = 0; k < 32; k++) {
            float4 bv = *(const float4*)&b_s[k * 68 + rc];
            ull b01 = pk2(bv.x, bv.y), b23 = pk2(bv.z, bv.w);
#pragma unroll
            for (int i = 0; i < 8; i++) {
                float xv = x_s[(tr + i) * 36 + k];
                ull xx = pk2(xv, xv);
                fma2(acc[i][0], xx, b01);
                fma2(acc[i][1], xx, b23);
            }
        }
    }
    size_t pb = (((size_t)b << 10) + t0 + tr) * 64 + rc;
#pragma unroll
    for (int i = 0; i < 8; i++) {
        float2 lo = upk2(acc[i][0]), hi = upk2(acc[i][1]);
        *(float4*)&g_proj[pb + (size_t)i * 64] = make_float4(lo.x, lo.y, hi.x, hi.y);
    }
    // combine per-token score halves
    sacc += __shfl_xor_sync(0xffffffffu, sacc, 1);
    if ((tid & 1) == 0) {
        int t = t0 + st_tok;
        g_score[(b << 10) + t] = (t == 0) ? -3.0e38f : sacc * (1.f / 1024.f);
    }
}

// ========== K3: per-batch top4 + detail + LayerNorm -> g_hb =================
__global__ void k_prep1(const float* __restrict__ x,
                        const float* __restrict__ lng, const float* __restrict__ lnb) {
    __shared__ float sc[1024];
    __shared__ float det[1024];
    __shared__ float rv[256];
    __shared__ int   ri[256];
    __shared__ int   topi[4];
    __shared__ float st2[2];
    int b = blockIdx.x, tid = threadIdx.x;

    for (int i = tid; i < 1024; i += 256) sc[i] = g_score[(b << 10) + i];
    __syncthreads();
    for (int rd = 0; rd < 4; rd++) {
        float bv = -3.4e38f; int bi = 1 << 30;
        for (int i = tid; i < 1024; i += 256) {
            float v = sc[i];
            if (v > bv || (v == bv && i < bi)) { bv = v; bi = i; }
        }
        rv[tid] = bv; ri[tid] = bi;
        __syncthreads();
        for (int off = 128; off; off >>= 1) {
            if (tid < off) {
                float v2 = rv[tid + off]; int i2 = ri[tid + off];
                if (v2 > rv[tid] || (v2 == rv[tid] && i2 < ri[tid])) { rv[tid] = v2; ri[tid] = i2; }
            }
            __syncthreads();
        }
        if (tid == 0) { topi[rd] = ri[0]; sc[ri[0]] = -3.4e38f; }
        __syncthreads();
    }
    int t0 = topi[0], t1 = topi[1], t2 = topi[2], t3 = topi[3];
    size_t xb = ((size_t)b << 20);
    for (int d = tid; d < 1024; d += 256)
        det[d] = 0.25f * (x[xb + ((size_t)t0 << 10) + d] + x[xb + ((size_t)t1 << 10) + d] +
                          x[xb + ((size_t)t2 << 10) + d] + x[xb + ((size_t)t3 << 10) + d]);
    __syncthreads();
    float s = 0.f, q = 0.f;
    for (int d = tid; d < 1024; d += 256) { float v = det[d]; s += v; q += v * v; }
    rv[tid] = s; __syncthreads();
    for (int off = 128; off; off >>= 1) { if (tid < off) rv[tid] += rv[tid + off]; __syncthreads(); }
    if (tid == 0) st2[0] = rv[0] * (1.f / 1024.f);
    __syncthreads();
    rv[tid] = q; __syncthreads();
    for (int off = 128; off; off >>= 1) { if (tid < off) rv[tid] += rv[tid + off]; __syncthreads(); }
    if (tid == 0) { float mu = st2[0]; st2[1] = rv[0] * (1.f / 1024.f) - mu * mu; }
    __syncthreads();
    float mu = st2[0], inv = rsqrtf(st2[1] + 1e-5f);
    for (int d = tid; d < 1024; d += 256)
        g_hb[(b << 10) + d] = (det[d] - mu) * inv * lng[d] + lnb[d];
}

// ========== K4: split-K small GEMM partial: (32 x CH) @ (CH x 64tile) =======
__global__ void k_sgK(const float* __restrict__ Aext, const float* __restrict__ W,
                      int N, int mode) {
    __shared__ __align__(16) float in_s[32 * 33];
    __shared__ __align__(16) float w_s[32 * 68];
    const float* A = (mode == 0) ? g_hb : (mode == 1) ? g_h1 : (mode == 2) ? Aext : g_lc;
    int lda = (mode == 0) ? 1024 : 512;
    int tid = threadIdx.x, n0 = blockIdx.x * 64;
    int kc0 = blockIdx.y * 128;
    int rg = (tid >> 4) << 1, cg = (tid & 15) << 2;
    float a[2][4] = {};
    for (int kc = kc0; kc < kc0 + 128; kc += 32) {
        __syncthreads();
#pragma unroll
        for (int s = 0; s < 4; s++) {
            int e = tid + (s << 8);
            int row = e >> 5, k = e & 31;
            in_s[k * 33 + row] = A[row * lda + kc + k];
        }
#pragma unroll
        for (int s = 0; s < 8; s++) {
            int e = tid + (s << 8);
            int k = e >> 6, nn = e & 63;
            w_s[k * 68 + nn] = W[(size_t)(kc + k) * N + n0 + nn];
        }
        __syncthreads();
#pragma unroll
        for (int k = 0; k < 32; k++) {
            float4 wv = *(const float4*)&w_s[k * 68 + cg];
            float i0 = in_s[k * 33 + rg], i1 = in_s[k * 33 + rg + 1];
            a[0][0] += i0 * wv.x; a[0][1] += i0 * wv.y; a[0][2] += i0 * wv.z; a[0][3] += i0 * wv.w;
            a[1][0] += i1 * wv.x; a[1][1] += i1 * wv.y; a[1][2] += i1 * wv.z; a[1][3] += i1 * wv.w;
        }
    }
    size_t pb = (size_t)blockIdx.y * 32 * N;
    int n = n0 + cg;
#pragma unroll
    for (int i = 0; i < 2; i++)
#pragma unroll
        for (int j = 0; j < 4; j++)
            g_part[pb + (size_t)(rg + i) * N + n + j] = a[i][j];
}

// ========== K5: reduce split-K partials + bias [+gelu] ======================
__global__ void k_red(const float* __restrict__ bias, int C, int N, int mode) {
    int e = blockIdx.x * 256 + threadIdx.x;
    if (e >= 32 * N) return;
    float s = 0.f;
    for (int c = 0; c < C; c++) s += g_part[(size_t)c * 32 * N + e];
    s += bias[e % N];
    if (mode == 0) s = 0.5f * s * (1.f + erff(s * 0.7071067811865475f));
    float* dst = (mode == 0) ? g_h1 : (mode == 1) ? g_lc : (mode == 2) ? g_G : g_L;
    dst[e] = s;
}

// ------------- 64x64 smem matmul, 256 threads, 4x4 tile (pad 68) ------------
__device__ __forceinline__ void mm64(float* __restrict__ C, const float* __restrict__ A,
                                     const float* __restrict__ Bm, int tid) {
    int i0 = (tid >> 4) << 2, j0 = (tid & 15) << 2;
    float a[4][4] = {};
#pragma unroll 4
    for (int m = 0; m < 64; m++) {
        float4 bv = *(const float4*)&Bm[m * 68 + j0];
        float r0 = A[(i0 + 0) * 68 + m], r1 = A[(i0 + 1) * 68 + m];
        float r2 = A[(i0 + 2) * 68 + m], r3 = A[(i0 + 3) * 68 + m];
        a[0][0] += r0 * bv.x; a[0][1] += r0 * bv.y; a[0][2] += r0 * bv.z; a[0][3] += r0 * bv.w;
        a[1][0] += r1 * bv.x; a[1][1] += r1 * bv.y; a[1][2] += r1 * bv.z; a[1][3] += r1 * bv.w;
        a[2][0] += r2 * bv.x; a[2][1] += r2 * bv.y; a[2][2] += r2 * bv.z; a[2][3] += r2 * bv.w;
        a[3][0] += r3 * bv.x; a[3][1] += r3 * bv.y; a[3][2] += r3 * bv.z; a[3][3] += r3 * bv.w;
    }
#pragma unroll
    for (int i = 0; i < 4; i++)
        *(float4*)&C[(i0 + i) * 68 + j0] = make_float4(a[i][0], a[i][1], a[i][2], a[i][3]);
}

// ========== K6: heads + omega + expm + Mb (per batch) =======================
__global__ void k_omega(const float* __restrict__ ctx,
                        const float* __restrict__ wm, const float* __restrict__ bm,
                        const float* __restrict__ wgain, const float* __restrict__ bgain,
                        const float* __restrict__ pwgate, const float* __restrict__ pbgate,
                        const float* __restrict__ pwa, const float* __restrict__ pba,
                        const float* __restrict__ pwb, const float* __restrict__ pbb) {
    extern __shared__ __align__(16) float sm[];
    float* fused = sm;             // 1024
    float* smm = sm + 1024;        // 64
    float* sgn = sm + 1088;        // 64
    float* red = sm + 1152;        // 256
    float* ssc = sm + 1408;        // 16
    float* B0 = sm + 1424;         // 6 buffers of 64*68
    float* B1 = B0 + 4352;
    float* B2 = B1 + 4352;
    float* B3 = B2 + 4352;
    float* B4 = B3 + 4352;
    float* B5 = B4 + 4352;
    int b = blockIdx.x, tid = threadIdx.x;

    for (int i = tid; i < 512; i += 256) {
        fused[i] = ctx[b * 512 + i];
        fused[512 + i] = g_lc[b * 512 + i];
    }
    __syncthreads();
    {   // mode mask + gains
        int r = tid & 63, qd = tid >> 6;
        float acc = 0.f;
        for (int i = qd * 256; i < qd * 256 + 256; i++) acc += fused[i] * wm[i * 64 + r];
        red[tid] = acc; __syncthreads();
        if (tid < 64) {
            float sv = red[tid] + red[tid + 64] + red[tid + 128] + red[tid + 192] + bm[tid];
            smm[tid] = 1.f / (1.f + expf(-sv));
        }
        __syncthreads();
        acc = 0.f;
        for (int i = qd * 256; i < qd * 256 + 256; i++) acc += fused[i] * wgain[i * 64 + r];
        red[tid] = acc; __syncthreads();
        if (tid < 64) {
            float sv = red[tid] + red[tid + 64] + red[tid + 128] + red[tid + 192] + bgain[tid];
            sgn[tid] = 1.f + 0.1f * tanhf(sv);
        }
        __syncthreads();
    }
    {   // scalar heads
        float pa = 0.f, pb = 0.f, pg = 0.f;
        for (int i = tid; i < 1024; i += 256) {
            float f = fused[i];
            pa += f * pwa[i]; pb += f * pwb[i]; pg += f * pwgate[i];
        }
        red[tid] = pa; __syncthreads();
        for (int off = 128; off; off >>= 1) { if (tid < off) red[tid] += red[tid + off]; __syncthreads(); }
        if (tid == 0) ssc[0] = red[0];
        __syncthreads();
        red[tid] = pb; __syncthreads();
        for (int off = 128; off; off >>= 1) { if (tid < off) red[tid] += red[tid + off]; __syncthreads(); }
        if (tid == 0) ssc[1] = red[0];
        __syncthreads();
        red[tid] = pg; __syncthreads();
        for (int off = 128; off; off >>= 1) { if (tid < off) red[tid] += red[tid + off]; __syncthreads(); }
        if (tid == 0) ssc[2] = red[0];
        __syncthreads();
    }
    float alpha = 0.5f / (1.f + expf(-(ssc[0] + pba[0])));
    float a2c = alpha * 0.5f;
    float b12 = 0.25f * tanhf(ssc[1] + pbb[0]) * (1.f / 12.f);
    float gate = 1.f / (1.f + expf(-(ssc[2] + pbgate[0])));

    {   // masked skews: B1 = mg, B2 = ml
        const float* Gp = g_G + b * 4096;
        const float* Lp = g_L + b * 4096;
        for (int e = tid; e < 4096; e += 256) {
            int i = e >> 6, j = e & 63;
            float w = smm[i] * smm[j];
            B1[i * 68 + j] = w * 0.5f * (Gp[i * 64 + j] - Gp[j * 64 + i]);
            B2[i * 68 + j] = w * 0.5f * (Lp[i * 64 + j] - Lp[j * 64 + i]);
        }
    }
    __syncthreads();
    mm64(B3, B2, B1, tid);   // P = ml @ mg; comm = P - P^T
    __syncthreads();
    for (int e = tid; e < 4096; e += 256) {
        int i = e >> 6, j = e & 63;
        B0[i * 68 + j] = a2c * (B1[i * 68 + j] + B2[i * 68 + j]) +
                         b12 * (B3[i * 68 + j] - B3[j * 68 + i]);
    }
    __syncthreads();
    // 1-norm and scaling
    if (tid < 64) {
        float sv = 0.f;
        for (int i = 0; i < 64; i++) sv += fabsf(B0[i * 68 + tid]);
        red[tid] = sv;
    }
    __syncthreads();
    for (int off = 32; off; off >>= 1) {
        if (tid < off && tid + off < 64) red[tid] = fmaxf(red[tid], red[tid + off]);
        __syncthreads();
    }
    float nrm = red[0];
    int sexp = 0;
    if (nrm > 0.5f) {
        sexp = (int)ceilf(log2f(nrm * 2.0f));
        if (sexp < 0) sexp = 0;
        if (sexp > 30) sexp = 30;
    }
    float scl = exp2f(-(float)sexp);
    for (int e = tid; e < 4096; e += 256) { int i = e >> 6, j = e & 63; B0[i * 68 + j] *= scl; }
    __syncthreads();
    // degree-8 Paterson-Stockmeyer Taylor
    mm64(B1, B0, B0, tid); __syncthreads();      // A2
    mm64(B2, B1, B0, tid); __syncthreads();      // A3
    mm64(B3, B1, B1, tid); __syncthreads();      // A4
    for (int e = tid; e < 4096; e += 256) {
        int i = e >> 6, j = e & 63;
        float dI = (i == j) ? 1.f : 0.f;
        B4[i * 68 + j] = dI * (1.f / 24.f) + B0[i * 68 + j] * (1.f / 120.f) +
                         B1[i * 68 + j] * (1.f / 720.f) + B2[i * 68 + j] * (1.f / 5040.f) +
                         B3[i * 68 + j] * (1.f / 40320.f);
    }
    __syncthreads();
    mm64(B5, B3, B4, tid); __syncthreads();      // A4*U
    for (int e = tid; e < 4096; e += 256) {
        int i = e >> 6, j = e & 63;
        float dI = (i == j) ? 1.f : 0.f;
        B3[i * 68 + j] = dI + B0[i * 68 + j] + 0.5f * B1[i * 68 + j] +
                         (1.f / 6.f) * B2[i * 68 + j] + B5[i * 68 + j];
    }
    __syncthreads();
    float* Tc = B3; float* Tw = B4;
    for (int it = 0; it < sexp; it++) {
        mm64(Tw, Tc, Tc, tid);
        __syncthreads();
        float* t = Tc; Tc = Tw; Tw = t;
    }
    // Mb = gate * (Q * diag(gains) - I)
    for (int e = tid; e < 4096; e += 256) {
        int i = e >> 6, j = e & 63;
        g_Mb[b * 4096 + e] = gate * (Tc[i * 68 + j] * sgn[j] - ((i == j) ? 1.f : 0.f));
    }
}

// ========== K7: C[b] = Mb[b] @ Bo  (64x64 @ 64x1024) ========================
__global__ void k_mbo(const float* __restrict__ Bo) {
    __shared__ __align__(16) float m_s[64 * 68];
    __shared__ __align__(16) float bo_s[64 * 68];
    int b = blockIdx.y, oc0 = blockIdx.x * 64, tid = threadIdx.x;
#pragma unroll
    for (int s = 0; s < 16; s++) {
        int e = tid + (s << 8);
        int i = e >> 6, j = e & 63;
        m_s[i * 68 + j] = g_Mb[b * 4096 + e];
        bo_s[i * 68 + j] = Bo[(size_t)i * 1024 + oc0 + j];
    }
    __syncthreads();
    int r0 = (tid >> 4) << 2, c0 = (tid & 15) << 2;
    float a[4][4] = {};
#pragma unroll 4
    for (int k = 0; k < 64; k++) {
        float4 bv = *(const float4*)&bo_s[k * 68 + c0];
        float m0 = m_s[(r0 + 0) * 68 + k], m1 = m_s[(r0 + 1) * 68 + k];
        float m2 = m_s[(r0 + 2) * 68 + k], m3 = m_s[(r0 + 3) * 68 + k];
        a[0][0] += m0 * bv.x; a[0][1] += m0 * bv.y; a[0][2] += m0 * bv.z; a[0][3] += m0 * bv.w;
        a[1][0] += m1 * bv.x; a[1][1] += m1 * bv.y; a[1][2] += m1 * bv.z; a[1][3] += m1 * bv.w;
        a[2][0] += m2 * bv.x; a[2][1] += m2 * bv.y; a[2][2] += m2 * bv.z; a[2][3] += m2 * bv.w;
        a[3][0] += m3 * bv.x; a[3][1] += m3 * bv.y; a[3][2] += m3 * bv.z; a[3][3] += m3 * bv.w;
    }
    size_t cb = ((size_t)b << 16);
#pragma unroll
    for (int i = 0; i < 4; i++)
        *(float4*)&g_C[cb + (size_t)(r0 + i) * 1024 + oc0 + c0] =
            make_float4(a[i][0], a[i][1], a[i][2], a[i][3]);
}

// ========== K8: out[b] = proj[b] @ C[b], k-pair FFMA2 =======================
// grid (16, 256): y -> b = y>>3, t0 = (y&7)*128
// a_s token-major [t][k] (LDS.64 gives contiguous k-pairs);
// c2u: C k-pairs packed at fill time: c2u[kp][r] = (C[2kp][r], C[2kp+1][r])
__global__ void k_fin(float* __restrict__ out) {
    extern __shared__ __align__(16) float smf[];
    float* a_s = smf;                         // 128 * 68 floats
    ull*   c2u = (ull*)(smf + 128 * 68);      // 32 * 64 ulls (16 KB)
    int oc0 = blockIdx.x * 64;
    int b = blockIdx.y >> 3;
    int t0 = (blockIdx.y & 7) << 7;
    size_t T0 = ((size_t)b << 10) + t0;
    size_t cb = ((size_t)b << 16);
    int tid = threadIdx.x;
    // proj tile: 128 tokens x 64 k, token-major (STS.128)
#pragma unroll
    for (int s = 0; s < 8; s++) {
        int e = tid + (s << 8);
        int t = e >> 4, kq = e & 15;
        float4 v = *(const float4*)&g_proj[(T0 + t) * 64 + (kq << 2)];
        *(float4*)&a_s[t * 68 + (kq << 2)] = v;
    }
    // C tile: 64 r x 64 oc -> k-pair packed ulls
#pragma unroll
    for (int s = 0; s < 2; s++) {
        int e = tid + (s << 8);
        int rp = e >> 4, cq = e & 15;          // rp in [0,32), 4 oc per task
        float4 va = *(const float4*)&g_C[cb + (size_t)(2 * rp)     * 1024 + oc0 + (cq << 2)];
        float4 vb = *(const float4*)&g_C[cb + (size_t)(2 * rp + 1) * 1024 + oc0 + (cq << 2)];
        c2u[rp * 64 + (cq << 2) + 0] = pk2(va.x, vb.x);
        c2u[rp * 64 + (cq << 2) + 1] = pk2(va.y, vb.y);
        c2u[rp * 64 + (cq << 2) + 2] = pk2(va.z, vb.z);
        c2u[rp * 64 + (cq << 2) + 3] = pk2(va.w, vb.w);
    }
    __syncthreads();
    int tr = (tid >> 4) << 3;      // 8 tokens
    int c0 = (tid & 15) << 2;      // 4 oc
    ull acc[8][4];
#pragma unroll
    for (int i = 0; i < 8; i++)
#pragma unroll
        for (int j = 0; j < 4; j++) acc[i][j] = 0ull;
#pragma unroll 4
    for (int kp = 0; kp < 32; kp++) {
        ulonglong2 cA = *(const ulonglong2*)&c2u[kp * 64 + c0];
        ulonglong2 cB = *(const ulonglong2*)&c2u[kp * 64 + c0 + 2];
#pragma unroll
        for (int i = 0; i < 8; i++) {
            ull xp = *(const ull*)&a_s[(tr + i) * 68 + 2 * kp];
            fma2(acc[i][0], xp, cA.x); fma2(acc[i][1], xp, cA.y);
            fma2(acc[i][2], xp, cB.x); fma2(acc[i][3], xp, cB.y);
        }
    }
#pragma unroll
    for (int i = 0; i < 8; i++) {
        float2 p0 = upk2(acc[i][0]), p1 = upk2(acc[i][1]);
        float2 p2 = upk2(acc[i][2]), p3 = upk2(acc[i][3]);
        *(float4*)&out[(T0 + tr + i) * 1024 + oc0 + c0] =
            make_float4(p0.x + p0.y, p1.x + p1.y, p2.x + p2.y, p3.x + p3.y);
    }
}

// =============================== launch =====================================
extern "C" void kernel_launch(void* const* d_in, const int* in_sizes, int n_in,
                              void* d_out, int out_size) {
    const float* x     = (const float*)d_in[0];
    const float* ctx   = (const float*)d_in[1];
    const float* Bi    = (const float*)d_in[2];
    const float* Bo    = (const float*)d_in[3];
    const float* lng   = (const float*)d_in[4];
    const float* lnb   = (const float*)d_in[5];
    const float* w1    = (const float*)d_in[6];
    const float* b1    = (const float*)d_in[7];
    const float* w2    = (const float*)d_in[8];
    const float* b2    = (const float*)d_in[9];
    const float* wg    = (const float*)d_in[10];
    const float* bg    = (const float*)d_in[11];
    const float* wl    = (const float*)d_in[12];
    const float* bl    = (const float*)d_in[13];
    const float* wm    = (const float*)d_in[14];
    const float* bm    = (const float*)d_in[15];
    const float* wgain = (const float*)d_in[16];
    const float* bgain = (const float*)d_in[17];
    const float* wgate = (const float*)d_in[18];
    const float* bgate = (const float*)d_in[19];
    const float* wa    = (const float*)d_in[20];
    const float* ba    = (const float*)d_in[21];
    const float* wb    = (const float*)d_in[22];
    const float* wbb   = (const float*)d_in[23];
    float* out = (float*)d_out;

    const int OMEGA_SMEM = (1424 + 6 * 4352) * 4;            // 110144 bytes
    const int FIN_SMEM   = 128 * 68 * 4 + 32 * 64 * 8;       // 34816 + 16384 = 51200
    cudaFuncSetAttribute(k_omega, cudaFuncAttributeMaxDynamicSharedMemorySize, OMEGA_SMEM);
    cudaFuncSetAttribute(k_fin,   cudaFuncAttributeMaxDynamicSharedMemorySize, FIN_SMEM);

    k_colsum<<<dim3(8, 32), 128>>>(x);
    k_proj<<<dim3(8, 32), 256>>>(x, Bi);
    k_prep1<<<32, 256>>>(x, lng, lnb);

    // MLP1: hb @ w1 (K=1024 -> 8 chunks), gelu
    k_sgK<<<dim3(8, 8), 256>>>(nullptr, w1, 512, 0);
    k_red<<<64, 256>>>(b1, 8, 512, 0);
    // MLP2: h1 @ w2 (K=512 -> 4 chunks)
    k_sgK<<<dim3(8, 4), 256>>>(nullptr, w2, 512, 1);
    k_red<<<64, 256>>>(b2, 4, 512, 1);
    // ctx @ wg -> G
    k_sgK<<<dim3(64, 4), 256>>>(ctx, wg, 4096, 2);
    k_red<<<512, 256>>>(bg, 4, 4096, 2);
    // lc @ wl -> L
    k_sgK<<<dim3(64, 4), 256>>>(nullptr, wl, 4096, 3);
    k_red<<<512, 256>>>(bl, 4, 4096, 3);

    k_omega<<<32, 256, OMEGA_SMEM>>>(ctx, wm, bm, wgain, bgain,
                                     wgate, bgate, wa, ba, wb, wbb);
    k_mbo<<<dim3(16, 32), 256>>>(Bo);
    k_fin<<<dim3(16, 256), 256, FIN_SMEM>>>(out);
}